// round 16
// baseline (speedup 1.0000x reference)
#include <cuda_runtime.h>
#include <cuda_fp16.h>
#include <cstdint>

#define NN 100000
#define EE 1600000
#define CC 128
#define EPS_ 1e-5f
#define NBLK ((NN + 255) / 256)   // 391

// ---------------- scratch ----------------
__device__ __align__(16) __half g_h[(size_t)NN * CC];   // fp16 intermediate features
__device__ __align__(16) float g_agg[(size_t)NN * CC];
__device__ __align__(16) float g_x1[(size_t)NN * CC];
__device__ float g_dinv[NN];
__device__ float g_as[NN];
__device__ float g_ad[NN];
__device__ float g_stats[2 * CC];
__device__ int g_is64;
__device__ int g_degc[NN];
__device__ int g_rowstart[NN];
__device__ int g_cur[NN];
__device__ int g_bsum[NBLK + 1];
__device__ int g_boff[NBLK + 1];
__device__ int g_csrc[EE];
__device__ __align__(16) unsigned g_Whi[16384];
__device__ __align__(16) unsigned g_Wlo[16384];

// load 4 consecutive half channels as float4
__device__ __forceinline__ float4 ldh4(const __half* p) {
    uint2 u = *(const uint2*)p;
    __half2 h0 = *(__half2*)&u.x;
    __half2 h1 = *(__half2*)&u.y;
    float2 f0 = __half22float2(h0);
    float2 f1 = __half22float2(h1);
    return make_float4(f0.x, f0.y, f1.x, f1.y);
}

// ---------------- edges dtype detection ----------------
__global__ void detect_dtype(const int* __restrict__ e32) {
    __shared__ int ok[256];
    int t = threadIdx.x;
    int all0 = 1;
#pragma unroll
    for (int i = 0; i < 2; i++) {
        int idx = 2 * (t + i * 256) + 1;
        if (e32[idx] != 0) all0 = 0;
    }
    ok[t] = all0;
    __syncthreads();
    for (int s = 128; s; s >>= 1) {
        if (t < s) ok[t] &= ok[t + s];
        __syncthreads();
    }
    if (t == 0) g_is64 = ok[0];
}

__device__ __forceinline__ int edge_src(const int* __restrict__ e32, int t) {
    return g_is64 ? e32[2 * t] : e32[t];
}
__device__ __forceinline__ int edge_dst(const int* __restrict__ e32, int t) {
    return g_is64 ? e32[2 * (EE + t)] : e32[EE + t];
}

// ---------------- CSR build ----------------
__global__ void zero_counts() {
    int i = blockIdx.x * blockDim.x + threadIdx.x;
    if (i < NN) g_degc[i] = 0;
}

__global__ void count_deg_kernel(const int* __restrict__ e32) {
    int t = blockIdx.x * blockDim.x + threadIdx.x;
    if (t < EE) atomicAdd(&g_degc[edge_dst(e32, t)], 1);
}

__global__ void dinv_kernel() {
    int i = blockIdx.x * blockDim.x + threadIdx.x;
    if (i < NN) g_dinv[i] = rsqrtf((float)(g_degc[i] + 1));
}

__global__ void scan1() {
    __shared__ int sm[256];
    int b = blockIdx.x, t = threadIdx.x;
    int idx = b * 256 + t;
    int v = (idx < NN) ? g_degc[idx] : 0;
    sm[t] = v;
    __syncthreads();
    for (int o = 1; o < 256; o <<= 1) {
        int add = (t >= o) ? sm[t - o] : 0;
        __syncthreads();
        sm[t] += add;
        __syncthreads();
    }
    if (idx < NN) g_rowstart[idx] = sm[t] - v;
    if (t == 255) g_bsum[b] = sm[255];
}

__global__ void scan2() {
    __shared__ int sm[512];
    int t = threadIdx.x;
    int v = (t < NBLK) ? g_bsum[t] : 0;
    sm[t] = v;
    __syncthreads();
    for (int o = 1; o < 512; o <<= 1) {
        int add = (t >= o) ? sm[t - o] : 0;
        __syncthreads();
        sm[t] += add;
        __syncthreads();
    }
    if (t < NBLK) g_boff[t] = sm[t] - v;
}

__global__ void scan3() {
    int idx = blockIdx.x * blockDim.x + threadIdx.x;
    if (idx < NN) {
        g_rowstart[idx] += g_boff[blockIdx.x];
        g_cur[idx] = 0;
    }
}

__global__ void fill_csr(const int* __restrict__ e32) {
    int t = blockIdx.x * blockDim.x + threadIdx.x;
    if (t >= EE) return;
    int s = edge_src(e32, t);
    int d = edge_dst(e32, t);
    int pos = g_rowstart[d] + atomicAdd(&g_cur[d], 1);
    g_csrc[pos] = s;
}

// ---------------- TF32 GEMM ----------------
#define MMA_TF32(c, a, b) \
    asm volatile("mma.sync.aligned.m16n8k8.row.col.f32.tf32.tf32.f32 " \
                 "{%0,%1,%2,%3},{%4,%5,%6,%7},{%8,%9},{%0,%1,%2,%3};" \
                 : "+f"((c)[0]), "+f"((c)[1]), "+f"((c)[2]), "+f"((c)[3]) \
                 : "r"((a)[0]), "r"((a)[1]), "r"((a)[2]), "r"((a)[3]), \
                   "r"((b)[0]), "r"((b)[1]))

__device__ __forceinline__ void tf32_split(float v, unsigned& hi, unsigned& lo) {
    asm("cvt.rna.tf32.f32 %0, %1;" : "=r"(hi) : "f"(v));
    float rem = v - __uint_as_float(hi);
    asm("cvt.rna.tf32.f32 %0, %1;" : "=r"(lo) : "f"(rem));
}

__global__ void split_W(const float* __restrict__ W) {
    int slot = blockIdx.x * 256 + threadIdx.x;   // 0..16383
    int rg = slot & 1;
    int lane = (slot >> 1) & 31;
    int nt = (slot >> 6) & 15;
    int kc = slot >> 10;
    int k = kc * 8 + rg * 4 + (lane & 3);
    int n = nt * 8 + (lane >> 2);
    unsigned hi, lo;
    tf32_split(W[k * 128 + n], hi, lo);
    g_Whi[slot] = hi;
    g_Wlo[slot] = lo;
}

// GEMM: 64-row tile, smem-staged A, pre-split W, 2 CTAs/SM. Output fp16 to g_h.
template <bool FROM_X1>
__device__ __forceinline__ void gemm_tf32_body(const float* __restrict__ Xext) {
    __shared__ float sX[64 * 68];   // 17.4 KB
    const float* X = FROM_X1 ? g_x1 : Xext;
    int row0 = blockIdx.x * 64;
    int tid = threadIdx.x;
    int w = tid >> 5, lane = tid & 31;
    int wm = w & 1, wn = w >> 1;
    int grp = lane >> 2, four = lane & 3;

    float acc[2][4][4];
#pragma unroll
    for (int mt = 0; mt < 2; mt++)
#pragma unroll
        for (int nt = 0; nt < 4; nt++)
#pragma unroll
            for (int c = 0; c < 4; c++) acc[mt][nt][c] = 0.f;

    int lr_base = wm * 32 + grp;

#pragma unroll
    for (int kch = 0; kch < 2; kch++) {
#pragma unroll
        for (int i = 0; i < 4; i++) {
            int idx = tid + i * 256;      // 0..1023
            int r = idx >> 4;             // 0..63
            int c4 = idx & 15;            // 0..15
            int gr = row0 + r;
            float4 v = (gr < NN) ? ((const float4*)(X + (size_t)gr * 128 + kch * 64))[c4]
                                 : make_float4(0.f, 0.f, 0.f, 0.f);
            *(float4*)(sX + r * 68 + c4 * 4) = v;
        }
        __syncthreads();

#pragma unroll
        for (int kc2 = 0; kc2 < 8; kc2++) {
            int kc = kch * 8 + kc2;
            unsigned bhi[4][2], blo[4][2];
#pragma unroll
            for (int nt = 0; nt < 4; nt++) {
                int ntg = wn * 4 + nt;
                int base = (kc * 16 + ntg) * 32 + lane;
                *(uint2*)bhi[nt] = ((const uint2*)g_Whi)[base];
                *(uint2*)blo[nt] = ((const uint2*)g_Wlo)[base];
            }
            int colb = kc2 * 8 + four;
#pragma unroll
            for (int mt = 0; mt < 2; mt++) {
                int r0 = lr_base + mt * 16;
                int r1 = r0 + 8;
                float f0 = sX[r0 * 68 + colb];
                float f1 = sX[r1 * 68 + colb];
                float f2 = sX[r0 * 68 + colb + 4];
                float f3 = sX[r1 * 68 + colb + 4];
                unsigned ahi[4], alo[4];
                tf32_split(f0, ahi[0], alo[0]);
                tf32_split(f1, ahi[1], alo[1]);
                tf32_split(f2, ahi[2], alo[2]);
                tf32_split(f3, ahi[3], alo[3]);
#pragma unroll
                for (int nt = 0; nt < 4; nt++) {
                    MMA_TF32(acc[mt][nt], ahi, bhi[nt]);
                    MMA_TF32(acc[mt][nt], alo, bhi[nt]);
                    MMA_TF32(acc[mt][nt], ahi, blo[nt]);
                }
            }
        }
        __syncthreads();
    }

#pragma unroll
    for (int mt = 0; mt < 2; mt++) {
        int r0 = row0 + lr_base + mt * 16;
        int r1 = r0 + 8;
#pragma unroll
        for (int nt = 0; nt < 4; nt++) {
            int coln = wn * 32 + nt * 8 + four * 2;
            if (r0 < NN)
                *(__half2*)(g_h + (size_t)r0 * 128 + coln) =
                    __floats2half2_rn(acc[mt][nt][0], acc[mt][nt][1]);
            if (r1 < NN)
                *(__half2*)(g_h + (size_t)r1 * 128 + coln) =
                    __floats2half2_rn(acc[mt][nt][2], acc[mt][nt][3]);
        }
    }
}

__global__ void __launch_bounds__(256, 2) gemm_tf32_A(const float* __restrict__ X) {
    gemm_tf32_body<false>(X);
}
__global__ void __launch_bounds__(256, 2) gemm_tf32_B() {
    gemm_tf32_body<true>(nullptr);
}

// ---------------- GCN gather: warp per dst, lane-cached edges ----------------
__global__ void __launch_bounds__(256) gather_gcn() {
    int d = (blockIdx.x * blockDim.x + threadIdx.x) >> 5;
    if (d >= NN) return;
    int lane = threadIdx.x & 31;
    int beg = g_rowstart[d];
    int deg = g_degc[d];
    float dd = g_dinv[d];

    int s_l = (lane < deg) ? g_csrc[beg + lane] : 0;
    float w_l = (lane < deg) ? g_dinv[s_l] * dd : 0.f;

    float4 acc = ldh4(g_h + (size_t)d * 128 + lane * 4);
    float w0 = dd * dd;
    acc.x *= w0; acc.y *= w0; acc.z *= w0; acc.w *= w0;

    int n32 = deg < 32 ? deg : 32;
    for (int j = 0; j < n32; j++) {
        int s = __shfl_sync(0xffffffffu, s_l, j);
        float w = __shfl_sync(0xffffffffu, w_l, j);
        float4 v = ldh4(g_h + (size_t)s * 128 + lane * 4);
        acc.x = fmaf(v.x, w, acc.x);
        acc.y = fmaf(v.y, w, acc.y);
        acc.z = fmaf(v.z, w, acc.z);
        acc.w = fmaf(v.w, w, acc.w);
    }
    for (int j = beg + 32; j < beg + deg; j++) {
        int s = g_csrc[j];
        float w = g_dinv[s] * dd;
        float4 v = ldh4(g_h + (size_t)s * 128 + lane * 4);
        acc.x = fmaf(v.x, w, acc.x);
        acc.y = fmaf(v.y, w, acc.y);
        acc.z = fmaf(v.z, w, acc.z);
        acc.w = fmaf(v.w, w, acc.w);
    }
    __stwt(((float4*)(g_agg + (size_t)d * 128)) + lane, acc);
}

// ---------------- column stats ----------------
__global__ void zero_stats() {
    int i = threadIdx.x;
    if (i < 2 * CC) g_stats[i] = 0.f;
}

__global__ void colstats(const float* __restrict__ bias) {
    __shared__ float s1[256], s2[256];
    int c = threadIdx.x & 127;
    int half_ = threadIdx.x >> 7;
    float b = bias[c];
    float acc = 0.f, acc2 = 0.f;
    for (int r = blockIdx.x * 2 + half_; r < NN; r += gridDim.x * 2) {
        float t = g_agg[(size_t)r * 128 + c] + b;
        acc += t;
        acc2 += t * t;
    }
    s1[threadIdx.x] = acc;
    s2[threadIdx.x] = acc2;
    __syncthreads();
    if (half_ == 0) {
        atomicAdd(&g_stats[c], s1[c] + s1[c + 128]);
        atomicAdd(&g_stats[128 + c], s2[c] + s2[c + 128]);
    }
}

// ---------------- finalize ----------------
template <bool PHASE_B>
__device__ __forceinline__ void finalize_body(const float* __restrict__ xin_ext,
                                              const float* __restrict__ bias,
                                              const float* __restrict__ gw,
                                              const float* __restrict__ gb,
                                              const float* __restrict__ gms,
                                              float* __restrict__ xout_ext) {
    int idx = blockIdx.x * blockDim.x + threadIdx.x;
    if (idx >= NN * CC) return;
    int c = idx & 127;
    float t = g_agg[idx] + bias[c];
    const float invn = 1.0f / (float)NN;
    float mean = g_stats[c] * invn;
    float a = gms[c] * mean;
    float var = g_stats[128 + c] * invn - 2.f * a * mean + a * a;
    float y = gw[c] * (t - a) * rsqrtf(var + EPS_) + gb[c];
    y = (y >= 0.f) ? y : 0.01f * y;
    float xv = PHASE_B ? g_x1[idx] : xin_ext[idx];
    float r = xv + y;
    if (PHASE_B) xout_ext[idx] = r;
    else g_x1[idx] = r;
}

__global__ void finalize_A(const float* __restrict__ xin, const float* __restrict__ bias,
                           const float* __restrict__ gw, const float* __restrict__ gb,
                           const float* __restrict__ gms) {
    finalize_body<false>(xin, bias, gw, gb, gms, nullptr);
}
__global__ void finalize_B(const float* __restrict__ bias, const float* __restrict__ gw,
                           const float* __restrict__ gb, const float* __restrict__ gms,
                           float* __restrict__ xout) {
    finalize_body<true>(nullptr, bias, gw, gb, gms, xout);
}

// ---------------- GAT attention dots ----------------
__global__ void attndot(const float* __restrict__ att_src, const float* __restrict__ att_dst) {
    int warp = (blockIdx.x * blockDim.x + threadIdx.x) >> 5;
    if (warp >= NN) return;
    int lane = threadIdx.x & 31;
    float4 hv = ldh4(g_h + (size_t)warp * 128 + lane * 4);
    float4 av = ((const float4*)att_src)[lane];
    float4 dv = ((const float4*)att_dst)[lane];
    float ps = hv.x * av.x + hv.y * av.y + hv.z * av.z + hv.w * av.w;
    float pd = hv.x * dv.x + hv.y * dv.y + hv.z * dv.z + hv.w * dv.w;
#pragma unroll
    for (int o = 16; o; o >>= 1) {
        ps += __shfl_xor_sync(0xffffffffu, ps, o);
        pd += __shfl_xor_sync(0xffffffffu, pd, o);
    }
    if (lane == 0) {
        g_as[warp] = ps;
        g_ad[warp] = pd;
    }
}

// ---------------- GAT gather (fused softmax, lane-cached) ----------------
__global__ void __launch_bounds__(256) gather_gat() {
    int d = (blockIdx.x * blockDim.x + threadIdx.x) >> 5;
    if (d >= NN) return;
    int lane = threadIdx.x & 31;
    int beg = g_rowstart[d];
    int deg = g_degc[d];
    float add = g_ad[d];
    float es = g_as[d] + add;
    es = (es >= 0.f) ? es : 0.2f * es;

    int s_l = (lane < deg) ? g_csrc[beg + lane] : 0;
    float e_l = -3.4e38f;
    if (lane < deg) {
        float e = g_as[s_l] + add;
        e_l = (e >= 0.f) ? e : 0.2f * e;
    }

    float m = fmaxf(es, e_l);
    for (int j = beg + 32 + lane; j < beg + deg; j += 32) {
        float e = g_as[g_csrc[j]] + add;
        e = (e >= 0.f) ? e : 0.2f * e;
        m = fmaxf(m, e);
    }
#pragma unroll
    for (int o = 16; o; o >>= 1) m = fmaxf(m, __shfl_xor_sync(0xffffffffu, m, o));

    float ex_l = (lane < deg) ? __expf(e_l - m) : 0.f;
    float part = ex_l;
    for (int j = beg + 32 + lane; j < beg + deg; j += 32) {
        float e = g_as[g_csrc[j]] + add;
        e = (e >= 0.f) ? e : 0.2f * e;
        part += __expf(e - m);
    }
#pragma unroll
    for (int o = 16; o; o >>= 1) part += __shfl_xor_sync(0xffffffffu, part, o);
    float ws = __expf(es - m);
    float rden = 1.0f / (part + ws);

    float4 acc = ldh4(g_h + (size_t)d * 128 + lane * 4);
    acc.x *= ws; acc.y *= ws; acc.z *= ws; acc.w *= ws;
    int n32 = deg < 32 ? deg : 32;
    for (int j = 0; j < n32; j++) {
        int s = __shfl_sync(0xffffffffu, s_l, j);
        float w = __shfl_sync(0xffffffffu, ex_l, j);
        float4 v = ldh4(g_h + (size_t)s * 128 + lane * 4);
        acc.x = fmaf(v.x, w, acc.x);
        acc.y = fmaf(v.y, w, acc.y);
        acc.z = fmaf(v.z, w, acc.z);
        acc.w = fmaf(v.w, w, acc.w);
    }
    for (int j = beg + 32; j < beg + deg; j++) {
        int s = g_csrc[j];
        float e = g_as[s] + add;
        e = (e >= 0.f) ? e : 0.2f * e;
        float w = __expf(e - m);
        float4 v = ldh4(g_h + (size_t)s * 128 + lane * 4);
        acc.x = fmaf(v.x, w, acc.x);
        acc.y = fmaf(v.y, w, acc.y);
        acc.z = fmaf(v.z, w, acc.z);
        acc.w = fmaf(v.w, w, acc.w);
    }
    acc.x *= rden; acc.y *= rden; acc.z *= rden; acc.w *= rden;
    __stwt(((float4*)(g_agg + (size_t)d * 128)) + lane, acc);
}

// ---------------- launch ----------------
extern "C" void kernel_launch(void* const* d_in, const int* in_sizes, int n_in,
                              void* d_out, int out_size) {
    const float* x = (const float*)d_in[0];
    const int* e32 = (const int*)d_in[1];
    const float* W1 = (const float*)d_in[2];
    const float* b1 = (const float*)d_in[3];
    const float* gn_w = (const float*)d_in[4];
    const float* gn_b = (const float*)d_in[5];
    const float* gn_ms = (const float*)d_in[6];
    const float* Wg = (const float*)d_in[7];
    const float* bg = (const float*)d_in[8];
    const float* att_src = (const float*)d_in[9];
    const float* att_dst = (const float*)d_in[10];
    float* out = (float*)d_out;

    const int TPB = 256;
    const int nb_node = NBLK;
    const int nb_edge = (EE + TPB - 1) / TPB;
    const int nb_warp_node = (NN * 32 + TPB - 1) / TPB;
    const int nb_elem = (NN * CC + TPB - 1) / TPB;
    const int gemm_blocks = (NN + 63) / 64;

    // position GEMM at launch #4 so ncu (-s 5 -c 1) profiles it
    detect_dtype<<<1, 256>>>(e32);                 // 1
    zero_counts<<<nb_node, TPB>>>();               // 2
    split_W<<<64, 256>>>(W1);                      // 3
    gemm_tf32_A<<<gemm_blocks, 256>>>(x);          // 4  <-- profiled
    count_deg_kernel<<<nb_edge, TPB>>>(e32);       // 5
    dinv_kernel<<<nb_node, TPB>>>();
    scan1<<<nb_node, 256>>>();
    scan2<<<1, 512>>>();
    scan3<<<nb_node, 256>>>();
    fill_csr<<<nb_edge, TPB>>>(e32);

    // ---- Phase A: GCN ----
    gather_gcn<<<nb_warp_node, TPB>>>();
    zero_stats<<<1, 256>>>();
    colstats<<<512, 256>>>(b1);
    finalize_A<<<nb_elem, TPB>>>(x, b1, gn_w, gn_b, gn_ms);

    // ---- Phase B: GAT ----
    split_W<<<64, 256>>>(Wg);
    gemm_tf32_B<<<gemm_blocks, 256>>>();
    attndot<<<nb_warp_node, TPB>>>(att_src, att_dst);
    gather_gat<<<nb_warp_node, TPB>>>();
    zero_stats<<<1, 256>>>();
    colstats<<<512, 256>>>(bg);
    finalize_B<<<nb_elem, TPB>>>(bg, gn_w, gn_b, gn_ms, out);
}

// round 17
// speedup vs baseline: 1.3039x; 1.3039x over previous
#include <cuda_runtime.h>
#include <cstdint>

#define NN 100000
#define EE 1600000
#define CC 128
#define EPS_ 1e-5f
#define NBLK ((NN + 255) / 256)   // 391

// ---------------- scratch ----------------
__device__ __align__(16) float g_h[(size_t)NN * CC];
__device__ __align__(16) float g_agg[(size_t)NN * CC];
__device__ __align__(16) float g_x1[(size_t)NN * CC];
__device__ float g_dinv[NN];
__device__ float g_as[NN];
__device__ float g_ad[NN];
__device__ float g_stats[2 * CC];
__device__ float g_statsB[2 * CC];
__device__ int g_is64;
__device__ int g_degc[NN];
__device__ int g_rowstart[NN];   // block-local exclusive prefix (add g_boff[d>>8])
__device__ int g_cur[NN];
__device__ int g_bsum[NBLK + 1];
__device__ int g_boff[NBLK + 1];
__device__ int g_csrc[EE];
__device__ __align__(16) unsigned g_Whi[16384];
__device__ __align__(16) unsigned g_Wlo[16384];

// ---------------- init: dtype detect + zero counters/cursors/stats ----------------
__global__ void init_all(const int* __restrict__ e32) {
    int i = blockIdx.x * blockDim.x + threadIdx.x;
    if (i < NN) {
        g_degc[i] = 0;
        g_cur[i] = 0;
    }
    if (i < 2 * CC) {
        g_stats[i] = 0.f;
        g_statsB[i] = 0.f;
    }
    if (blockIdx.x == 0) {
        __shared__ int ok[256];
        int t = threadIdx.x;
        int all0 = 1;
#pragma unroll
        for (int k = 0; k < 2; k++) {
            int idx = 2 * (t + k * 256) + 1;
            if (e32[idx] != 0) all0 = 0;
        }
        ok[t] = all0;
        __syncthreads();
        for (int s = 128; s; s >>= 1) {
            if (t < s) ok[t] &= ok[t + s];
            __syncthreads();
        }
        if (t == 0) g_is64 = ok[0];
    }
}

__device__ __forceinline__ int edge_src(const int* __restrict__ e32, int t) {
    return g_is64 ? e32[2 * t] : e32[t];
}
__device__ __forceinline__ int edge_dst(const int* __restrict__ e32, int t) {
    return g_is64 ? e32[2 * (EE + t)] : e32[EE + t];
}

// ---------------- CSR build ----------------
__global__ void count_deg_kernel(const int* __restrict__ e32) {
    int t = blockIdx.x * blockDim.x + threadIdx.x;
    if (t < EE) atomicAdd(&g_degc[edge_dst(e32, t)], 1);
}

// block-local exclusive scan of degc + dinv; per-block totals to g_bsum
__global__ void scan1() {
    __shared__ int sm[256];
    int b = blockIdx.x, t = threadIdx.x;
    int idx = b * 256 + t;
    int v = (idx < NN) ? g_degc[idx] : 0;
    if (idx < NN) g_dinv[idx] = rsqrtf((float)(v + 1));
    sm[t] = v;
    __syncthreads();
    for (int o = 1; o < 256; o <<= 1) {
        int add = (t >= o) ? sm[t - o] : 0;
        __syncthreads();
        sm[t] += add;
        __syncthreads();
    }
    if (idx < NN) g_rowstart[idx] = sm[t] - v;
    if (t == 255) g_bsum[b] = sm[255];
}

__global__ void scan2() {
    __shared__ int sm[512];
    int t = threadIdx.x;
    int v = (t < NBLK) ? g_bsum[t] : 0;
    sm[t] = v;
    __syncthreads();
    for (int o = 1; o < 512; o <<= 1) {
        int add = (t >= o) ? sm[t - o] : 0;
        __syncthreads();
        sm[t] += add;
        __syncthreads();
    }
    if (t < NBLK) g_boff[t] = sm[t] - v;
}

__device__ __forceinline__ int row_start(int d) {
    return g_rowstart[d] + g_boff[d >> 8];
}

__global__ void fill_csr(const int* __restrict__ e32) {
    int t = blockIdx.x * blockDim.x + threadIdx.x;
    if (t >= EE) return;
    int s = edge_src(e32, t);
    int d = edge_dst(e32, t);
    int pos = row_start(d) + atomicAdd(&g_cur[d], 1);
    g_csrc[pos] = s;
}

// ---------------- TF32 GEMM ----------------
#define MMA_TF32(c, a, b) \
    asm volatile("mma.sync.aligned.m16n8k8.row.col.f32.tf32.tf32.f32 " \
                 "{%0,%1,%2,%3},{%4,%5,%6,%7},{%8,%9},{%0,%1,%2,%3};" \
                 : "+f"((c)[0]), "+f"((c)[1]), "+f"((c)[2]), "+f"((c)[3]) \
                 : "r"((a)[0]), "r"((a)[1]), "r"((a)[2]), "r"((a)[3]), \
                   "r"((b)[0]), "r"((b)[1]))

__device__ __forceinline__ void tf32_split(float v, unsigned& hi, unsigned& lo) {
    asm("cvt.rna.tf32.f32 %0, %1;" : "=r"(hi) : "f"(v));
    float rem = v - __uint_as_float(hi);
    asm("cvt.rna.tf32.f32 %0, %1;" : "=r"(lo) : "f"(rem));
}

__global__ void split_W(const float* __restrict__ W) {
    int slot = blockIdx.x * 256 + threadIdx.x;   // 0..16383
    int rg = slot & 1;
    int lane = (slot >> 1) & 31;
    int nt = (slot >> 6) & 15;
    int kc = slot >> 10;
    int k = kc * 8 + rg * 4 + (lane & 3);
    int n = nt * 8 + (lane >> 2);
    unsigned hi, lo;
    tf32_split(W[k * 128 + n], hi, lo);
    g_Whi[slot] = hi;
    g_Wlo[slot] = lo;
}

// GEMM: 64-row tile, smem-staged A, pre-split W, 2 CTAs/SM.
// ATTN: fuse attndot (g_as/g_ad) into epilogue using register accumulators.
template <bool FROM_X1, bool ATTN>
__device__ __forceinline__ void gemm_tf32_body(const float* __restrict__ Xext,
                                               const float* __restrict__ att_src,
                                               const float* __restrict__ att_dst) {
    __shared__ float sX[64 * 68];   // 17.4 KB
    __shared__ float sAsrc[128], sAdst[128];
    __shared__ float sAS[64][4], sAD[64][4];
    const float* X = FROM_X1 ? g_x1 : Xext;
    int row0 = blockIdx.x * 64;
    int tid = threadIdx.x;
    int w = tid >> 5, lane = tid & 31;
    int wm = w & 1, wn = w >> 1;
    int grp = lane >> 2, four = lane & 3;

    if (ATTN) {
        if (tid < 128) sAsrc[tid] = att_src[tid];
        else sAdst[tid - 128] = att_dst[tid - 128];
    }

    float acc[2][4][4];
#pragma unroll
    for (int mt = 0; mt < 2; mt++)
#pragma unroll
        for (int nt = 0; nt < 4; nt++)
#pragma unroll
            for (int c = 0; c < 4; c++) acc[mt][nt][c] = 0.f;

    int lr_base = wm * 32 + grp;

#pragma unroll
    for (int kch = 0; kch < 2; kch++) {
#pragma unroll
        for (int i = 0; i < 4; i++) {
            int idx = tid + i * 256;      // 0..1023
            int r = idx >> 4;             // 0..63
            int c4 = idx & 15;            // 0..15
            int gr = row0 + r;
            float4 v = (gr < NN) ? ((const float4*)(X + (size_t)gr * 128 + kch * 64))[c4]
                                 : make_float4(0.f, 0.f, 0.f, 0.f);
            *(float4*)(sX + r * 68 + c4 * 4) = v;
        }
        __syncthreads();

#pragma unroll
        for (int kc2 = 0; kc2 < 8; kc2++) {
            int kc = kch * 8 + kc2;
            unsigned bhi[4][2], blo[4][2];
#pragma unroll
            for (int nt = 0; nt < 4; nt++) {
                int ntg = wn * 4 + nt;
                int base = (kc * 16 + ntg) * 32 + lane;
                *(uint2*)bhi[nt] = ((const uint2*)g_Whi)[base];
                *(uint2*)blo[nt] = ((const uint2*)g_Wlo)[base];
            }
            int colb = kc2 * 8 + four;
#pragma unroll
            for (int mt = 0; mt < 2; mt++) {
                int r0 = lr_base + mt * 16;
                int r1 = r0 + 8;
                float f0 = sX[r0 * 68 + colb];
                float f1 = sX[r1 * 68 + colb];
                float f2 = sX[r0 * 68 + colb + 4];
                float f3 = sX[r1 * 68 + colb + 4];
                unsigned ahi[4], alo[4];
                tf32_split(f0, ahi[0], alo[0]);
                tf32_split(f1, ahi[1], alo[1]);
                tf32_split(f2, ahi[2], alo[2]);
                tf32_split(f3, ahi[3], alo[3]);
#pragma unroll
                for (int nt = 0; nt < 4; nt++) {
                    MMA_TF32(acc[mt][nt], ahi, bhi[nt]);
                    MMA_TF32(acc[mt][nt], alo, bhi[nt]);
                    MMA_TF32(acc[mt][nt], ahi, blo[nt]);
                }
            }
        }
        __syncthreads();
    }

    // store h
#pragma unroll
    for (int mt = 0; mt < 2; mt++) {
        int r0 = row0 + lr_base + mt * 16;
        int r1 = r0 + 8;
#pragma unroll
        for (int nt = 0; nt < 4; nt++) {
            int coln = wn * 32 + nt * 8 + four * 2;
            if (r0 < NN)
                *(float2*)(g_h + (size_t)r0 * 128 + coln) = make_float2(acc[mt][nt][0], acc[mt][nt][1]);
            if (r1 < NN)
                *(float2*)(g_h + (size_t)r1 * 128 + coln) = make_float2(acc[mt][nt][2], acc[mt][nt][3]);
        }
    }

    if (ATTN) {
        float asum[2][2], adsum[2][2];   // [mt][r0/r1]
#pragma unroll
        for (int mt = 0; mt < 2; mt++) {
            asum[mt][0] = asum[mt][1] = 0.f;
            adsum[mt][0] = adsum[mt][1] = 0.f;
        }
#pragma unroll
        for (int mt = 0; mt < 2; mt++)
#pragma unroll
            for (int nt = 0; nt < 4; nt++) {
                int coln = wn * 32 + nt * 8 + four * 2;
                float a0 = sAsrc[coln], a1 = sAsrc[coln + 1];
                float b0 = sAdst[coln], b1 = sAdst[coln + 1];
                asum[mt][0] += acc[mt][nt][0] * a0 + acc[mt][nt][1] * a1;
                asum[mt][1] += acc[mt][nt][2] * a0 + acc[mt][nt][3] * a1;
                adsum[mt][0] += acc[mt][nt][0] * b0 + acc[mt][nt][1] * b1;
                adsum[mt][1] += acc[mt][nt][2] * b0 + acc[mt][nt][3] * b1;
            }
        // quad reduce (over lanes with same grp)
#pragma unroll
        for (int o = 1; o <= 2; o <<= 1) {
#pragma unroll
            for (int mt = 0; mt < 2; mt++) {
                asum[mt][0] += __shfl_xor_sync(0xffffffffu, asum[mt][0], o);
                asum[mt][1] += __shfl_xor_sync(0xffffffffu, asum[mt][1], o);
                adsum[mt][0] += __shfl_xor_sync(0xffffffffu, adsum[mt][0], o);
                adsum[mt][1] += __shfl_xor_sync(0xffffffffu, adsum[mt][1], o);
            }
        }
        if (four == 0) {
#pragma unroll
            for (int mt = 0; mt < 2; mt++) {
                int lr0 = wm * 32 + mt * 16 + grp;
                sAS[lr0][wn] = asum[mt][0];
                sAS[lr0 + 8][wn] = asum[mt][1];
                sAD[lr0][wn] = adsum[mt][0];
                sAD[lr0 + 8][wn] = adsum[mt][1];
            }
        }
        __syncthreads();
        if (tid < 64) {
            int gr = row0 + tid;
            if (gr < NN) g_as[gr] = sAS[tid][0] + sAS[tid][1] + sAS[tid][2] + sAS[tid][3];
        } else if (tid < 128) {
            int lr = tid - 64;
            int gr = row0 + lr;
            if (gr < NN) g_ad[gr] = sAD[lr][0] + sAD[lr][1] + sAD[lr][2] + sAD[lr][3];
        }
    }
}

__global__ void __launch_bounds__(256, 2) gemm_tf32_A(const float* __restrict__ X) {
    gemm_tf32_body<false, false>(X, nullptr, nullptr);
}
__global__ void __launch_bounds__(256, 2) gemm_tf32_B(const float* __restrict__ att_src,
                                                      const float* __restrict__ att_dst) {
    gemm_tf32_body<true, true>(nullptr, att_src, att_dst);
}

// ---------------- GCN gather: warp per dst, lane-cached edges ----------------
__global__ void __launch_bounds__(256) gather_gcn() {
    int d = (blockIdx.x * blockDim.x + threadIdx.x) >> 5;
    if (d >= NN) return;
    int lane = threadIdx.x & 31;
    int beg = row_start(d);
    int deg = g_degc[d];
    float dd = g_dinv[d];

    int s_l = (lane < deg) ? g_csrc[beg + lane] : 0;
    float w_l = (lane < deg) ? g_dinv[s_l] * dd : 0.f;

    float4 acc = ((const float4*)(g_h + (size_t)d * 128))[lane];
    float w0 = dd * dd;
    acc.x *= w0; acc.y *= w0; acc.z *= w0; acc.w *= w0;

    int n32 = deg < 32 ? deg : 32;
    for (int j = 0; j < n32; j++) {
        int s = __shfl_sync(0xffffffffu, s_l, j);
        float w = __shfl_sync(0xffffffffu, w_l, j);
        float4 v = ((const float4*)(g_h + (size_t)s * 128))[lane];
        acc.x = fmaf(v.x, w, acc.x);
        acc.y = fmaf(v.y, w, acc.y);
        acc.z = fmaf(v.z, w, acc.z);
        acc.w = fmaf(v.w, w, acc.w);
    }
    for (int j = beg + 32; j < beg + deg; j++) {
        int s = g_csrc[j];
        float w = g_dinv[s] * dd;
        float4 v = ((const float4*)(g_h + (size_t)s * 128))[lane];
        acc.x = fmaf(v.x, w, acc.x);
        acc.y = fmaf(v.y, w, acc.y);
        acc.z = fmaf(v.z, w, acc.z);
        acc.w = fmaf(v.w, w, acc.w);
    }
    __stwt(((float4*)(g_agg + (size_t)d * 128)) + lane, acc);
}

// ---------------- column stats (phase selects stats array) ----------------
__global__ void colstats(const float* __restrict__ bias, int phase) {
    __shared__ float s1[256], s2[256];
    float* st = phase ? g_statsB : g_stats;
    int c = threadIdx.x & 127;
    int half_ = threadIdx.x >> 7;
    float b = bias[c];
    float acc = 0.f, acc2 = 0.f;
    for (int r = blockIdx.x * 2 + half_; r < NN; r += gridDim.x * 2) {
        float t = g_agg[(size_t)r * 128 + c] + b;
        acc += t;
        acc2 += t * t;
    }
    s1[threadIdx.x] = acc;
    s2[threadIdx.x] = acc2;
    __syncthreads();
    if (half_ == 0) {
        atomicAdd(&st[c], s1[c] + s1[c + 128]);
        atomicAdd(&st[128 + c], s2[c] + s2[c + 128]);
    }
}

// ---------------- finalize ----------------
template <bool PHASE_B>
__device__ __forceinline__ void finalize_body(const float* __restrict__ xin_ext,
                                              const float* __restrict__ bias,
                                              const float* __restrict__ gw,
                                              const float* __restrict__ gb,
                                              const float* __restrict__ gms,
                                              float* __restrict__ xout_ext) {
    int idx = blockIdx.x * blockDim.x + threadIdx.x;
    if (idx >= NN * CC) return;
    int c = idx & 127;
    const float* st = PHASE_B ? g_statsB : g_stats;
    float t = g_agg[idx] + bias[c];
    const float invn = 1.0f / (float)NN;
    float mean = st[c] * invn;
    float a = gms[c] * mean;
    float var = st[128 + c] * invn - 2.f * a * mean + a * a;
    float y = gw[c] * (t - a) * rsqrtf(var + EPS_) + gb[c];
    y = (y >= 0.f) ? y : 0.01f * y;
    float xv = PHASE_B ? g_x1[idx] : xin_ext[idx];
    float r = xv + y;
    if (PHASE_B) xout_ext[idx] = r;
    else g_x1[idx] = r;
}

__global__ void finalize_A(const float* __restrict__ xin, const float* __restrict__ bias,
                           const float* __restrict__ gw, const float* __restrict__ gb,
                           const float* __restrict__ gms) {
    finalize_body<false>(xin, bias, gw, gb, gms, nullptr);
}
__global__ void finalize_B(const float* __restrict__ bias, const float* __restrict__ gw,
                           const float* __restrict__ gb, const float* __restrict__ gms,
                           float* __restrict__ xout) {
    finalize_body<true>(nullptr, bias, gw, gb, gms, xout);
}

// ---------------- GAT gather (fused softmax, lane-cached) ----------------
__global__ void __launch_bounds__(256) gather_gat() {
    int d = (blockIdx.x * blockDim.x + threadIdx.x) >> 5;
    if (d >= NN) return;
    int lane = threadIdx.x & 31;
    int beg = row_start(d);
    int deg = g_degc[d];
    float add = g_ad[d];
    float es = g_as[d] + add;
    es = (es >= 0.f) ? es : 0.2f * es;

    int s_l = (lane < deg) ? g_csrc[beg + lane] : 0;
    float e_l = -3.4e38f;
    if (lane < deg) {
        float e = g_as[s_l] + add;
        e_l = (e >= 0.f) ? e : 0.2f * e;
    }

    float m = fmaxf(es, e_l);
    for (int j = beg + 32 + lane; j < beg + deg; j += 32) {
        float e = g_as[g_csrc[j]] + add;
        e = (e >= 0.f) ? e : 0.2f * e;
        m = fmaxf(m, e);
    }
#pragma unroll
    for (int o = 16; o; o >>= 1) m = fmaxf(m, __shfl_xor_sync(0xffffffffu, m, o));

    float ex_l = (lane < deg) ? __expf(e_l - m) : 0.f;
    float part = ex_l;
    for (int j = beg + 32 + lane; j < beg + deg; j += 32) {
        float e = g_as[g_csrc[j]] + add;
        e = (e >= 0.f) ? e : 0.2f * e;
        part += __expf(e - m);
    }
#pragma unroll
    for (int o = 16; o; o >>= 1) part += __shfl_xor_sync(0xffffffffu, part, o);
    float ws = __expf(es - m);
    float rden = 1.0f / (part + ws);

    float4 acc = ((const float4*)(g_h + (size_t)d * 128))[lane];
    acc.x *= ws; acc.y *= ws; acc.z *= ws; acc.w *= ws;
    int n32 = deg < 32 ? deg : 32;
    for (int j = 0; j < n32; j++) {
        int s = __shfl_sync(0xffffffffu, s_l, j);
        float w = __shfl_sync(0xffffffffu, ex_l, j);
        float4 v = ((const float4*)(g_h + (size_t)s * 128))[lane];
        acc.x = fmaf(v.x, w, acc.x);
        acc.y = fmaf(v.y, w, acc.y);
        acc.z = fmaf(v.z, w, acc.z);
        acc.w = fmaf(v.w, w, acc.w);
    }
    for (int j = beg + 32; j < beg + deg; j++) {
        int s = g_csrc[j];
        float e = g_as[s] + add;
        e = (e >= 0.f) ? e : 0.2f * e;
        float w = __expf(e - m);
        float4 v = ((const float4*)(g_h + (size_t)s * 128))[lane];
        acc.x = fmaf(v.x, w, acc.x);
        acc.y = fmaf(v.y, w, acc.y);
        acc.z = fmaf(v.z, w, acc.z);
        acc.w = fmaf(v.w, w, acc.w);
    }
    acc.x *= rden; acc.y *= rden; acc.z *= rden; acc.w *= rden;
    __stwt(((float4*)(g_agg + (size_t)d * 128)) + lane, acc);
}

// ---------------- launch ----------------
extern "C" void kernel_launch(void* const* d_in, const int* in_sizes, int n_in,
                              void* d_out, int out_size) {
    const float* x = (const float*)d_in[0];
    const int* e32 = (const int*)d_in[1];
    const float* W1 = (const float*)d_in[2];
    const float* b1 = (const float*)d_in[3];
    const float* gn_w = (const float*)d_in[4];
    const float* gn_b = (const float*)d_in[5];
    const float* gn_ms = (const float*)d_in[6];
    const float* Wg = (const float*)d_in[7];
    const float* bg = (const float*)d_in[8];
    const float* att_src = (const float*)d_in[9];
    const float* att_dst = (const float*)d_in[10];
    float* out = (float*)d_out;

    const int TPB = 256;
    const int nb_node = NBLK;
    const int nb_edge = (EE + TPB - 1) / TPB;
    const int nb_warp_node = (NN * 32 + TPB - 1) / TPB;
    const int nb_elem = (NN * CC + TPB - 1) / TPB;
    const int gemm_blocks = (NN + 63) / 64;

    // keep gemm_A at launch #4 (ncu profiles it)
    init_all<<<nb_node, TPB>>>(e32);               // 1
    split_W<<<64, 256>>>(W1);                      // 2
    count_deg_kernel<<<nb_edge, TPB>>>(e32);       // 3
    gemm_tf32_A<<<gemm_blocks, 256>>>(x);          // 4  <-- profiled
    scan1<<<nb_node, 256>>>();                     // 5
    scan2<<<1, 512>>>();                           // 6
    fill_csr<<<nb_edge, TPB>>>(e32);               // 7

    // ---- Phase A: GCN ----
    gather_gcn<<<nb_warp_node, TPB>>>();           // 8
    colstats<<<512, 256>>>(b1, 0);                 // 9
    finalize_A<<<nb_elem, TPB>>>(x, b1, gn_w, gn_b, gn_ms);   // 10

    // ---- Phase B: GAT ----
    split_W<<<64, 256>>>(Wg);                      // 11
    gemm_tf32_B<<<gemm_blocks, 256>>>(att_src, att_dst);      // 12 (fused attndot)
    gather_gat<<<nb_warp_node, TPB>>>();           // 13
    colstats<<<512, 256>>>(bg, 1);                 // 14
    finalize_B<<<nb_elem, TPB>>>(bg, gn_w, gn_b, gn_ms, out); // 15
}